// round 1
// baseline (speedup 1.0000x reference)
#include <cuda_runtime.h>

// out[b,s,e] = sum_h cs[b,s,e,h] * W[e,h] + bias[e]
// B=4, S=512, E=64, H=1024  -> ROWS = 131072 reductions over 1024 contiguous floats.
// Pure HBM-streaming problem: one warp per row, float4 vectorized, warp-shuffle reduce.

#define E_DIM 64
#define H_DIM 1024
#define HV4   (H_DIM / 4)      // 256 float4 per row
#define WARPS_PER_BLOCK 8

__global__ __launch_bounds__(WARPS_PER_BLOCK * 32)
void Cell_to_Entity_78735340470739_kernel(
    const float4* __restrict__ cs,    // [ROWS, HV4]
    const float4* __restrict__ W,     // [E, HV4]
    const float*  __restrict__ bias,  // [E]
    float*        __restrict__ out)   // [ROWS]
{
    const int warp = threadIdx.x >> 5;
    const int lane = threadIdx.x & 31;
    const int row  = blockIdx.x * WARPS_PER_BLOCK + warp;

    const int e = row & (E_DIM - 1);

    const float4* __restrict__ x = cs + (size_t)row * HV4;
    const float4* __restrict__ w = W  + (size_t)e   * HV4;

    float acc = 0.0f;
#pragma unroll
    for (int i = 0; i < 8; ++i) {
        const int idx = lane + 32 * i;
        float4 a = x[idx];          // streaming HBM read, coalesced 512B/warp/iter
        float4 b = __ldg(&w[idx]);  // hot in L1/L2 (256 KiB total W)
        acc += a.x * b.x + a.y * b.y + a.z * b.z + a.w * b.w;
    }

    // warp reduction
#pragma unroll
    for (int off = 16; off > 0; off >>= 1)
        acc += __shfl_xor_sync(0xffffffffu, acc, off);

    if (lane == 0)
        out[row] = acc + __ldg(&bias[e]);
}

extern "C" void kernel_launch(void* const* d_in, const int* in_sizes, int n_in,
                              void* d_out, int out_size)
{
    const float4* cs   = (const float4*)d_in[0];   // [B,S,E,H] float32
    const float4* W    = (const float4*)d_in[1];   // [E,H]     float32
    const float*  bias = (const float*)d_in[2];    // [E]       float32
    float*        out  = (float*)d_out;            // [B,S,E]   float32

    const int rows = out_size;                     // B*S*E = 131072
    const int blocks = rows / WARPS_PER_BLOCK;     // 16384

    Cell_to_Entity_78735340470739_kernel<<<blocks, WARPS_PER_BLOCK * 32>>>(cs, W, bias, out);
}

// round 2
// speedup vs baseline: 1.0257x; 1.0257x over previous
#include <cuda_runtime.h>

// out[b,s,e] = sum_h cs[b,s,e,h] * W[e,h] + bias[e]
// B=4, S=512, E=64, H=1024  -> ROWS = 131072 reductions over 1024 contiguous floats.
// HBM-bound streaming: one warp per row, float4 vectorized, warp-shuffle reduce.
// R2: 128-thr blocks (better occupancy granularity), __ldcs streaming hint on cs
//     so the one-pass stream doesn't evict the hot W rows from L1.

#define E_DIM 64
#define H_DIM 1024
#define HV4   (H_DIM / 4)      // 256 float4 per row
#define WARPS_PER_BLOCK 4

__device__ __forceinline__ float4 ldcs_f4(const float4* p) {
    float4 v;
    asm volatile("ld.global.cs.v4.f32 {%0,%1,%2,%3}, [%4];"
                 : "=f"(v.x), "=f"(v.y), "=f"(v.z), "=f"(v.w)
                 : "l"(p));
    return v;
}

__global__ __launch_bounds__(WARPS_PER_BLOCK * 32)
void Cell_to_Entity_78735340470739_kernel(
    const float4* __restrict__ cs,    // [ROWS, HV4]
    const float4* __restrict__ W,     // [E, HV4]
    const float*  __restrict__ bias,  // [E]
    float*        __restrict__ out)   // [ROWS]
{
    const int warp = threadIdx.x >> 5;
    const int lane = threadIdx.x & 31;
    const int row  = blockIdx.x * WARPS_PER_BLOCK + warp;

    const int e = row & (E_DIM - 1);

    const float4* __restrict__ x = cs + (size_t)row * HV4;
    const float4* __restrict__ w = W  + (size_t)e   * HV4;

    float acc = 0.0f;
#pragma unroll
    for (int i = 0; i < 8; ++i) {
        const int idx = lane + 32 * i;
        float4 a = ldcs_f4(&x[idx]);   // streaming, evict-first: one-pass data
        float4 b = __ldg(&w[idx]);     // hot in L1/L2 (256 KiB total W)
        acc += a.x * b.x + a.y * b.y + a.z * b.z + a.w * b.w;
    }

    // warp reduction
#pragma unroll
    for (int off = 16; off > 0; off >>= 1)
        acc += __shfl_xor_sync(0xffffffffu, acc, off);

    if (lane == 0)
        out[row] = acc + __ldg(&bias[e]);
}

extern "C" void kernel_launch(void* const* d_in, const int* in_sizes, int n_in,
                              void* d_out, int out_size)
{
    const float4* cs   = (const float4*)d_in[0];   // [B,S,E,H] float32
    const float4* W    = (const float4*)d_in[1];   // [E,H]     float32
    const float*  bias = (const float*)d_in[2];    // [E]       float32
    float*        out  = (float*)d_out;            // [B,S,E]   float32

    const int rows = out_size;                     // B*S*E = 131072
    const int blocks = rows / WARPS_PER_BLOCK;     // 32768

    Cell_to_Entity_78735340470739_kernel<<<blocks, WARPS_PER_BLOCK * 32>>>(cs, W, bias, out);
}